// round 8
// baseline (speedup 1.0000x reference)
#include <cuda_runtime.h>
#include <cuda_bf16.h>
#include <cstdint>

// Problem constants
#define BATCH   2048
#define SEQ     28
#define DMODEL  1024
#define NHEAD   16
#define DHEAD   64
#define RROWS   (BATCH * SEQ)          // 57344
#define RC      (RROWS * DMODEL)       // 58,720,256 elements

// Scratch (device globals: allocation-free rule)
__device__ float g_h  [RC];
__device__ float g_q  [RC];
__device__ float g_k  [RC];
__device__ float g_v  [RC];
__device__ float g_ctx[RC];

// ---------------------------------------------------------------------------
// LayerNorm: one block per row of 1024
// ---------------------------------------------------------------------------
__global__ __launch_bounds__(256) void ln_kernel(const float* __restrict__ x,
                                                 const float* __restrict__ gamma,
                                                 const float* __restrict__ beta)
{
    int row = blockIdx.x;
    int tid = threadIdx.x;
    const float4* xr = (const float4*)(x + (size_t)row * DMODEL);
    float4 v = xr[tid];

    float s = v.x + v.y + v.z + v.w;
    float q = v.x * v.x + v.y * v.y + v.z * v.z + v.w * v.w;
    #pragma unroll
    for (int o = 16; o; o >>= 1) {
        s += __shfl_xor_sync(0xffffffffu, s, o);
        q += __shfl_xor_sync(0xffffffffu, q, o);
    }
    __shared__ float ss[8], sq[8];
    int wid = tid >> 5, lane = tid & 31;
    if (lane == 0) { ss[wid] = s; sq[wid] = q; }
    __syncthreads();
    __shared__ float s_mean, s_rstd;
    if (tid == 0) {
        float S = 0.f, Q = 0.f;
        #pragma unroll
        for (int i = 0; i < 8; ++i) { S += ss[i]; Q += sq[i]; }
        float mean = S * (1.0f / DMODEL);
        float var  = Q * (1.0f / DMODEL) - mean * mean;
        s_mean = mean;
        s_rstd = rsqrtf(var + 1e-5f);
    }
    __syncthreads();
    float mean = s_mean, rstd = s_rstd;

    float4 gv = ((const float4*)gamma)[tid];
    float4 bv = ((const float4*)beta)[tid];
    float4 o;
    o.x = (v.x - mean) * rstd * gv.x + bv.x;
    o.y = (v.y - mean) * rstd * gv.y + bv.y;
    o.z = (v.z - mean) * rstd * gv.z + bv.z;
    o.w = (v.w - mean) * rstd * gv.w + bv.w;
    ((float4*)(g_h + (size_t)row * DMODEL))[tid] = o;
}

// ---------------------------------------------------------------------------
// TF32 GEMM: C[57344 x 1024] = A[57344 x 1024] * B[1024 x 1024] (+ resid)
// Tile 128x128x32, 256 threads (8 warps as 2x4), mma.sync m16n8k8 tf32.
// Fragments via ldmatrix.x4 on k-contiguous xor-swizzled smem tiles.
// Double-buffered smem (64KB dynamic): one __syncthreads per BK-iter.
// ---------------------------------------------------------------------------
#define BM 128
#define BN 128
#define BK 32
// word offsets inside dynamic smem
#define ABUF_WORDS (BM * BK)              // 4096 words = 16KB per buffer
#define BBUF_WORDS (BN * BK)              // 4096 words
#define BS_WORD_OFF (2 * ABUF_WORDS)      // Bs starts after both A buffers
#define SMEM_BYTES  (4 * ABUF_WORDS * 4)  // 64 KB total

__device__ __forceinline__ unsigned f2tf(float x)
{
    unsigned u;
    asm("cvt.rna.tf32.f32 %0, %1;" : "=r"(u) : "f"(x));
    return u;
}

__device__ __forceinline__ void mma_tf32(float c[4],
                                         unsigned a0, unsigned a1, unsigned a2, unsigned a3,
                                         unsigned b0, unsigned b1)
{
    asm volatile(
        "mma.sync.aligned.m16n8k8.row.col.f32.tf32.tf32.f32 "
        "{%0,%1,%2,%3}, {%4,%5,%6,%7}, {%8,%9}, {%0,%1,%2,%3};"
        : "+f"(c[0]), "+f"(c[1]), "+f"(c[2]), "+f"(c[3])
        : "r"(a0), "r"(a1), "r"(a2), "r"(a3), "r"(b0), "r"(b1));
}

__device__ __forceinline__ void ldsm4(unsigned& r0, unsigned& r1, unsigned& r2, unsigned& r3,
                                      uint32_t addr)
{
    asm volatile("ldmatrix.sync.aligned.m8n8.x4.shared.b16 {%0,%1,%2,%3}, [%4];"
                 : "=r"(r0), "=r"(r1), "=r"(r2), "=r"(r3) : "r"(addr));
}

// smem tiles: [row][k] with 128B rows (32 tf32), 16B-chunk xor swizzle by row&7
__device__ __forceinline__ void gemm_body(const float* __restrict__ A,
                                          const float* __restrict__ B,
                                          float* __restrict__ C,
                                          const float* __restrict__ resid,
                                          int mt, int nt)
{
    extern __shared__ unsigned sm[];
    unsigned* AsBuf = sm;                   // [2][BM*BK]
    unsigned* BsBuf = sm + BS_WORD_OFF;     // [2][BN*BK]

    const int tid  = threadIdx.x;
    const int wid  = tid >> 5;
    const int lane = tid & 31;
    const int wm   = (wid & 1) * 64;
    const int wn   = (wid >> 1) * 32;
    const int g    = lane >> 2;
    const int r    = lane & 3;

    const int gm = mt * BM;
    const int gn = nt * BN;

    // ---- A staging map: thread loads float4 along k ----
    const int a_m = tid >> 3;                 // 0..31 (+32*it)
    const int a_k = (tid & 7) * 4;            // 0,4,...,28
    const int a_chunk = (tid & 7) ^ (a_m & 7);  // constant per thread

    // ---- B staging map: thread gathers 4 k-scalars for one n ----
    const int b_n  = tid & 31;                // 0..31 (+32*it)
    const int b_k4 = (tid >> 5) * 4;          // 0,4,...,28
    const int b_chunk = (tid >> 5) ^ (b_n & 7);

    // ---- ldmatrix per-lane addressing ----
    const uint32_t smBase = (uint32_t)__cvta_generic_to_shared(sm);
    const uint32_t asBase0 = smBase;                       // A buf 0
    const uint32_t bsBase0 = smBase + BS_WORD_OFF * 4;     // B buf 0
    const int lrow = lane & 15;
    const int lhi  = lane >> 4;               // 0/1: k-chunk select
    const int am7  = (wm + lrow) & 7;
    const int bn7  = (wn + lrow) & 7;
    // byte address = bufBase + row*128 + ((2*ks + lhi) ^ row7)*16

    // ---- global prefetch (first tile) ----
    float4 pa[4];
    float  pbv[4][4];
    {
        const float* Ap = A + (size_t)(gm + a_m) * DMODEL + a_k;
        #pragma unroll
        for (int it = 0; it < 4; ++it)
            pa[it] = *(const float4*)(Ap + (size_t)(32 * it) * DMODEL);
        #pragma unroll
        for (int it = 0; it < 4; ++it)
            #pragma unroll
            for (int j = 0; j < 4; ++j)
                pbv[it][j] = B[(size_t)(b_k4 + j) * DMODEL + gn + b_n + 32 * it];
    }

    // ---- stage tile 0 into buffer 0 ----
    #pragma unroll
    for (int it = 0; it < 4; ++it) {
        uint4 ta;
        ta.x = f2tf(pa[it].x); ta.y = f2tf(pa[it].y);
        ta.z = f2tf(pa[it].z); ta.w = f2tf(pa[it].w);
        *(uint4*)&AsBuf[(a_m + 32 * it) * BK + a_chunk * 4] = ta;
        uint4 tb;
        tb.x = f2tf(pbv[it][0]); tb.y = f2tf(pbv[it][1]);
        tb.z = f2tf(pbv[it][2]); tb.w = f2tf(pbv[it][3]);
        *(uint4*)&BsBuf[(b_n + 32 * it) * BK + b_chunk * 4] = tb;
    }
    __syncthreads();

    float acc[4][4][4];
    #pragma unroll
    for (int i = 0; i < 4; ++i)
        #pragma unroll
        for (int j = 0; j < 4; ++j)
            #pragma unroll
            for (int t = 0; t < 4; ++t) acc[i][j][t] = 0.f;

    const int KT = DMODEL / BK;   // 32
    for (int kt = 0; kt < KT; ++kt) {
        const int cur = kt & 1;
        const uint32_t asb = asBase0 + (uint32_t)cur * (ABUF_WORDS * 4);
        const uint32_t bsb = bsBase0 + (uint32_t)cur * (BBUF_WORDS * 4);

        // issue global loads for next tile early (overlap with compute)
        if (kt < KT - 1) {
            const float* Ap = A + (size_t)(gm + a_m) * DMODEL + (kt + 1) * BK + a_k;
            #pragma unroll
            for (int it = 0; it < 4; ++it)
                pa[it] = *(const float4*)(Ap + (size_t)(32 * it) * DMODEL);
            #pragma unroll
            for (int it = 0; it < 4; ++it)
                #pragma unroll
                for (int j = 0; j < 4; ++j)
                    pbv[it][j] = B[(size_t)((kt + 1) * BK + b_k4 + j) * DMODEL + gn + b_n + 32 * it];
        }

        // compute current buffer: fragments via ldmatrix.x4
        #pragma unroll
        for (int ks = 0; ks < 4; ++ks) {
            unsigned af[4][4], bf[4][2];
            #pragma unroll
            for (int i = 0; i < 4; ++i) {
                uint32_t addr = asb + (uint32_t)((wm + 16 * i + lrow) * 128)
                              + (uint32_t)((((2 * ks) + lhi) ^ am7) * 16);
                ldsm4(af[i][0], af[i][1], af[i][2], af[i][3], addr);
            }
            #pragma unroll
            for (int jp = 0; jp < 2; ++jp) {
                uint32_t addr = bsb + (uint32_t)((wn + 16 * jp + lrow) * 128)
                              + (uint32_t)((((2 * ks) + lhi) ^ bn7) * 16);
                // mats: {rows 0-7, rows 8-15} x {k 0-3, k 4-7}
                ldsm4(bf[2 * jp][0], bf[2 * jp + 1][0],
                      bf[2 * jp][1], bf[2 * jp + 1][1], addr);
            }
            #pragma unroll
            for (int i = 0; i < 4; ++i)
                #pragma unroll
                for (int j = 0; j < 4; ++j)
                    mma_tf32(acc[i][j], af[i][0], af[i][1], af[i][2], af[i][3],
                             bf[j][0], bf[j][1]);
        }

        // stage next tile into the other buffer, then one barrier
        if (kt < KT - 1) {
            unsigned* An = AsBuf + (cur ^ 1) * ABUF_WORDS;
            unsigned* Bn = BsBuf + (cur ^ 1) * BBUF_WORDS;
            #pragma unroll
            for (int it = 0; it < 4; ++it) {
                uint4 ta;
                ta.x = f2tf(pa[it].x); ta.y = f2tf(pa[it].y);
                ta.z = f2tf(pa[it].z); ta.w = f2tf(pa[it].w);
                *(uint4*)&An[(a_m + 32 * it) * BK + a_chunk * 4] = ta;
                uint4 tb;
                tb.x = f2tf(pbv[it][0]); tb.y = f2tf(pbv[it][1]);
                tb.z = f2tf(pbv[it][2]); tb.w = f2tf(pbv[it][3]);
                *(uint4*)&Bn[(b_n + 32 * it) * BK + b_chunk * 4] = tb;
            }
            __syncthreads();
        }
    }

    // epilogue
    #pragma unroll
    for (int i = 0; i < 4; ++i) {
        #pragma unroll
        for (int j = 0; j < 4; ++j) {
            const int row = gm + wm + 16 * i + g;
            const int col = gn + wn + 8 * j + 2 * r;
            float2 v0 = make_float2(acc[i][j][0], acc[i][j][1]);
            float2 v1 = make_float2(acc[i][j][2], acc[i][j][3]);
            if (resid) {
                float2 r0 = *(const float2*)&resid[(size_t)row * DMODEL + col];
                float2 r1 = *(const float2*)&resid[(size_t)(row + 8) * DMODEL + col];
                v0.x += r0.x; v0.y += r0.y;
                v1.x += r1.x; v1.y += r1.y;
            }
            *(float2*)&C[(size_t)row * DMODEL + col]       = v0;
            *(float2*)&C[(size_t)(row + 8) * DMODEL + col] = v1;
        }
    }
}

__global__ __launch_bounds__(256, 2) void gemm_qkv_kernel(const float* __restrict__ wq,
                                                          const float* __restrict__ wk,
                                                          const float* __restrict__ wv)
{
    const int mat = blockIdx.x >> 3;
    const float* B = (mat == 0) ? wq : (mat == 1) ? wk : wv;
    float* C = (mat == 0) ? g_q : (mat == 1) ? g_k : g_v;
    gemm_body(g_h, B, C, nullptr, blockIdx.y, blockIdx.x & 7);
}

__global__ __launch_bounds__(256, 2) void gemm_out_kernel(const float* __restrict__ wo,
                                                          float* __restrict__ out)
{
    gemm_body(g_ctx, wo, out, g_h, blockIdx.y, blockIdx.x);
}

// ---------------------------------------------------------------------------
// Attention: one block per (b, h). scores 28x28 + teeth bias, softmax, ctx.
// ---------------------------------------------------------------------------
__global__ __launch_bounds__(256) void attn_kernel()
{
    const int h = blockIdx.x;
    const int b = blockIdx.y;
    __shared__ float sq[SEQ][65], sk[SEQ][65], sv[SEQ][65];
    __shared__ float sp[SEQ][29];

    const int tid = threadIdx.x;
    const size_t base = (size_t)b * SEQ * DMODEL + (size_t)h * DHEAD;

    for (int idx = tid; idx < SEQ * (DHEAD / 4); idx += 256) {
        const int row = idx >> 4;            // 0..27
        const int c   = (idx & 15) * 4;      // 0..60
        const size_t gofs = base + (size_t)row * DMODEL + c;
        float4 qv = *(const float4*)(g_q + gofs);
        float4 kv = *(const float4*)(g_k + gofs);
        float4 vv = *(const float4*)(g_v + gofs);
        sq[row][c] = qv.x; sq[row][c + 1] = qv.y; sq[row][c + 2] = qv.z; sq[row][c + 3] = qv.w;
        sk[row][c] = kv.x; sk[row][c + 1] = kv.y; sk[row][c + 2] = kv.z; sk[row][c + 3] = kv.w;
        sv[row][c] = vv.x; sv[row][c + 1] = vv.y; sv[row][c + 2] = vv.z; sv[row][c + 3] = vv.w;
    }
    __syncthreads();

    const float slope = exp2f(-0.5f * (float)(h + 1));

    for (int e = tid; e < SEQ * SEQ; e += 256) {
        const int i = e / SEQ;
        const int j = e - i * SEQ;
        float acc = 0.f;
        #pragma unroll
        for (int d = 0; d < DHEAD; ++d) acc += sq[i][d] * sk[j][d];
        int dc = (i % 14) - (j % 14); if (dc < 0) dc = -dc;
        int dr = (i / 14) - (j / 14); if (dr < 0) dr = -dr;
        sp[i][j] = acc + slope * (float)(dc + dr);
    }
    __syncthreads();

    if (tid < SEQ) {
        float m = -1e30f;
        #pragma unroll
        for (int j = 0; j < SEQ; ++j) m = fmaxf(m, sp[tid][j]);
        float s = 0.f;
        float e[SEQ];
        #pragma unroll
        for (int j = 0; j < SEQ; ++j) { e[j] = __expf(sp[tid][j] - m); s += e[j]; }
        const float inv = 1.0f / s;
        #pragma unroll
        for (int j = 0; j < SEQ; ++j) sp[tid][j] = e[j] * inv;
    }
    __syncthreads();

    for (int e = tid; e < SEQ * DHEAD; e += 256) {
        const int i = e >> 6;
        const int d = e & 63;
        float acc = 0.f;
        #pragma unroll
        for (int j = 0; j < SEQ; ++j) acc += sp[i][j] * sv[j][d];
        g_ctx[base + (size_t)i * DMODEL + d] = acc;
    }
}

// ---------------------------------------------------------------------------
// Launch
// ---------------------------------------------------------------------------
extern "C" void kernel_launch(void* const* d_in, const int* in_sizes, int n_in,
                              void* d_out, int out_size)
{
    const float* hidden = (const float*)d_in[0];
    const float* wq     = (const float*)d_in[1];
    const float* wk     = (const float*)d_in[2];
    const float* wv     = (const float*)d_in[3];
    const float* wo     = (const float*)d_in[4];
    const float* gamma  = (const float*)d_in[5];
    const float* beta   = (const float*)d_in[6];
    float* out = (float*)d_out;

    // 64KB dynamic smem for the double-buffered GEMMs. Called unconditionally
    // every launch (idempotent, host-side, capture-legal) — no static guards
    // per the harness determinism rules.
    cudaFuncSetAttribute(gemm_qkv_kernel,
                         cudaFuncAttributeMaxDynamicSharedMemorySize, SMEM_BYTES);
    cudaFuncSetAttribute(gemm_out_kernel,
                         cudaFuncAttributeMaxDynamicSharedMemorySize, SMEM_BYTES);

    ln_kernel<<<RROWS, 256>>>(hidden, gamma, beta);
    gemm_qkv_kernel<<<dim3(24, RROWS / BM), 256, SMEM_BYTES>>>(wq, wk, wv);
    attn_kernel<<<dim3(NHEAD, BATCH), 256>>>();
    gemm_out_kernel<<<dim3(8, RROWS / BM), 256, SMEM_BYTES>>>(wo, out);
}

// round 11
// speedup vs baseline: 1.8940x; 1.8940x over previous
#include <cuda_runtime.h>
#include <cuda_bf16.h>
#include <cstdint>

// Problem constants
#define BATCH   2048
#define SEQ     28
#define DMODEL  1024
#define NHEAD   16
#define DHEAD   64
#define RROWS   (BATCH * SEQ)          // 57344
#define RC      (RROWS * DMODEL)       // 58,720,256 elements

// Scratch (device globals: allocation-free rule)
__device__ float g_h  [RC];            // exact LN output (residual source)
__device__ float g_ha [RC];            // tf32-rounded LN output (GEMM A)
__device__ float g_q  [RC];
__device__ float g_k  [RC];
__device__ float g_v  [RC];
__device__ float g_ctx[RC];            // tf32-rounded ctx (GEMM A)
// tf32-rounded, transposed weights: wt[n][k]
__device__ float g_wqt[DMODEL * DMODEL];
__device__ float g_wkt[DMODEL * DMODEL];
__device__ float g_wvt[DMODEL * DMODEL];
__device__ float g_wot[DMODEL * DMODEL];

__device__ __forceinline__ unsigned f2tf(float x)
{
    unsigned u;
    asm("cvt.rna.tf32.f32 %0, %1;" : "=r"(u) : "f"(x));
    return u;
}

// ---------------------------------------------------------------------------
// Weight prep: transpose + tf32-round. w[k][n] -> wt[n][k]. grid (32,32,4), block (32,8)
// ---------------------------------------------------------------------------
__global__ __launch_bounds__(256) void prep_weights_kernel(const float* __restrict__ wq,
                                                           const float* __restrict__ wk,
                                                           const float* __restrict__ wv,
                                                           const float* __restrict__ wo)
{
    __shared__ float t[32][33];
    const int mat = blockIdx.z;
    const float* src = (mat == 0) ? wq : (mat == 1) ? wk : (mat == 2) ? wv : wo;
    float* dst = (mat == 0) ? g_wqt : (mat == 1) ? g_wkt : (mat == 2) ? g_wvt : g_wot;
    const int n0 = blockIdx.x * 32, k0 = blockIdx.y * 32;
    const int tx = threadIdx.x, ty = threadIdx.y;
    #pragma unroll
    for (int i = 0; i < 4; ++i)
        t[ty + 8 * i][tx] = src[(size_t)(k0 + ty + 8 * i) * DMODEL + n0 + tx];
    __syncthreads();
    #pragma unroll
    for (int i = 0; i < 4; ++i)
        dst[(size_t)(n0 + ty + 8 * i) * DMODEL + k0 + tx] =
            __uint_as_float(f2tf(t[tx][ty + 8 * i]));
}

// ---------------------------------------------------------------------------
// LayerNorm: one block per row of 1024. Writes exact g_h and rounded g_ha.
// ---------------------------------------------------------------------------
__global__ __launch_bounds__(256) void ln_kernel(const float* __restrict__ x,
                                                 const float* __restrict__ gamma,
                                                 const float* __restrict__ beta)
{
    int row = blockIdx.x;
    int tid = threadIdx.x;
    const float4* xr = (const float4*)(x + (size_t)row * DMODEL);
    float4 v = xr[tid];

    float s = v.x + v.y + v.z + v.w;
    float q = v.x * v.x + v.y * v.y + v.z * v.z + v.w * v.w;
    #pragma unroll
    for (int o = 16; o; o >>= 1) {
        s += __shfl_xor_sync(0xffffffffu, s, o);
        q += __shfl_xor_sync(0xffffffffu, q, o);
    }
    __shared__ float ss[8], sq[8];
    int wid = tid >> 5, lane = tid & 31;
    if (lane == 0) { ss[wid] = s; sq[wid] = q; }
    __syncthreads();
    __shared__ float s_mean, s_rstd;
    if (tid == 0) {
        float S = 0.f, Q = 0.f;
        #pragma unroll
        for (int i = 0; i < 8; ++i) { S += ss[i]; Q += sq[i]; }
        float mean = S * (1.0f / DMODEL);
        float var  = Q * (1.0f / DMODEL) - mean * mean;
        s_mean = mean;
        s_rstd = rsqrtf(var + 1e-5f);
    }
    __syncthreads();
    float mean = s_mean, rstd = s_rstd;

    float4 gv = ((const float4*)gamma)[tid];
    float4 bv = ((const float4*)beta)[tid];
    float4 o;
    o.x = (v.x - mean) * rstd * gv.x + bv.x;
    o.y = (v.y - mean) * rstd * gv.y + bv.y;
    o.z = (v.z - mean) * rstd * gv.z + bv.z;
    o.w = (v.w - mean) * rstd * gv.w + bv.w;
    ((float4*)(g_h + (size_t)row * DMODEL))[tid] = o;
    float4 oa;
    oa.x = __uint_as_float(f2tf(o.x));
    oa.y = __uint_as_float(f2tf(o.y));
    oa.z = __uint_as_float(f2tf(o.z));
    oa.w = __uint_as_float(f2tf(o.w));
    ((float4*)(g_ha + (size_t)row * DMODEL))[tid] = oa;
}

// ---------------------------------------------------------------------------
// TF32 GEMM: C[57344 x 1024] = A[57344 x 1024] * Bt^T (+ resid)
// A and Bt are pre-rounded to tf32; Bt is [n][k] k-contiguous.
// Tile 128x128x32, 256 threads, mma.sync m16n8k8 tf32.
// Staging via cp.async 16B (zero staging registers); double-buffered smem;
// fragments via ldmatrix.x4 on xor-swizzled k-contiguous tiles.
// ---------------------------------------------------------------------------
#define BM 128
#define BN 128
#define BK 32
#define ABYTES (BM * BK * 4)            // 16 KB per A buffer
#define SMEM_BYTES (4 * ABYTES)         // A0 A1 B0 B1 = 64 KB

__device__ __forceinline__ void mma_tf32(float c[4],
                                         unsigned a0, unsigned a1, unsigned a2, unsigned a3,
                                         unsigned b0, unsigned b1)
{
    asm volatile(
        "mma.sync.aligned.m16n8k8.row.col.f32.tf32.tf32.f32 "
        "{%0,%1,%2,%3}, {%4,%5,%6,%7}, {%8,%9}, {%0,%1,%2,%3};"
        : "+f"(c[0]), "+f"(c[1]), "+f"(c[2]), "+f"(c[3])
        : "r"(a0), "r"(a1), "r"(a2), "r"(a3), "r"(b0), "r"(b1));
}

__device__ __forceinline__ void ldsm4(unsigned& r0, unsigned& r1, unsigned& r2, unsigned& r3,
                                      uint32_t addr)
{
    asm volatile("ldmatrix.sync.aligned.m8n8.x4.shared.b16 {%0,%1,%2,%3}, [%4];"
                 : "=r"(r0), "=r"(r1), "=r"(r2), "=r"(r3) : "r"(addr));
}

__device__ __forceinline__ void cp16(uint32_t dst, const float* src)
{
    asm volatile("cp.async.cg.shared.global [%0], [%1], 16;" :: "r"(dst), "l"(src));
}

__device__ __forceinline__ void gemm_body(const float* __restrict__ A,
                                          const float* __restrict__ Bt,
                                          float* __restrict__ C,
                                          const float* __restrict__ resid,
                                          int mt, int nt)
{
    extern __shared__ unsigned sm[];

    const int tid  = threadIdx.x;
    const int wid  = tid >> 5;
    const int lane = tid & 31;
    const int wm   = (wid & 1) * 64;
    const int wn   = (wid >> 1) * 32;
    const int g    = lane >> 2;
    const int r    = lane & 3;

    const int gm = mt * BM;
    const int gn = nt * BN;

    // staging map (same for A and Bt: both k-contiguous, 128B rows)
    const int s_row   = tid >> 3;                   // 0..31 (+32*it)
    const int s_k     = (tid & 7) * 4;              // element k offset 0..28
    const int s_chunk = (tid & 7) ^ (s_row & 7);    // swizzled 16B chunk

    const uint32_t smBase  = (uint32_t)__cvta_generic_to_shared(sm);
    const uint32_t asBase0 = smBase;                 // A bufs at 0, ABYTES
    const uint32_t bsBase0 = smBase + 2 * ABYTES;    // B bufs at 2*, 3*ABYTES

    // ldmatrix per-lane addressing
    const int lrow = lane & 15;
    const int lhi  = lane >> 4;
    const int am7  = (wm + lrow) & 7;
    const int bn7  = (wn + lrow) & 7;

    const float* Ap = A  + (size_t)(gm + s_row) * DMODEL + s_k;
    const float* Bp = Bt + (size_t)(gn + s_row) * DMODEL + s_k;
    const uint32_t dstOff = (uint32_t)(s_row * 128 + s_chunk * 16);

    const int KT = DMODEL / BK;   // 32

    // stage tile 0 into buffer 0
    {
        #pragma unroll
        for (int it = 0; it < 4; ++it) {
            cp16(asBase0 + dstOff + (uint32_t)(32 * it) * 128, Ap + (size_t)(32 * it) * DMODEL);
            cp16(bsBase0 + dstOff + (uint32_t)(32 * it) * 128, Bp + (size_t)(32 * it) * DMODEL);
        }
        asm volatile("cp.async.commit_group;");
    }

    float acc[4][4][4];
    #pragma unroll
    for (int i = 0; i < 4; ++i)
        #pragma unroll
        for (int j = 0; j < 4; ++j)
            #pragma unroll
            for (int t = 0; t < 4; ++t) acc[i][j][t] = 0.f;

    for (int kt = 0; kt < KT; ++kt) {
        const int cur = kt & 1;

        // stage next tile into the other buffer
        if (kt < KT - 1) {
            const uint32_t an = asBase0 + (uint32_t)(cur ^ 1) * ABYTES + dstOff;
            const uint32_t bn = bsBase0 + (uint32_t)(cur ^ 1) * ABYTES + dstOff;
            const float* An = Ap + (size_t)(kt + 1) * BK;
            const float* Bn = Bp + (size_t)(kt + 1) * BK;
            #pragma unroll
            for (int it = 0; it < 4; ++it) {
                cp16(an + (uint32_t)(32 * it) * 128, An + (size_t)(32 * it) * DMODEL);
                cp16(bn + (uint32_t)(32 * it) * 128, Bn + (size_t)(32 * it) * DMODEL);
            }
            asm volatile("cp.async.commit_group;");
            asm volatile("cp.async.wait_group 1;" ::: "memory");
        } else {
            asm volatile("cp.async.wait_group 0;" ::: "memory");
        }
        __syncthreads();

        const uint32_t asb = asBase0 + (uint32_t)cur * ABYTES;
        const uint32_t bsb = bsBase0 + (uint32_t)cur * ABYTES;

        // compute current buffer: fragments via ldmatrix.x4
        #pragma unroll
        for (int ks = 0; ks < 4; ++ks) {
            unsigned af[4][4], bf[4][2];
            #pragma unroll
            for (int i = 0; i < 4; ++i) {
                uint32_t addr = asb + (uint32_t)((wm + 16 * i + lrow) * 128)
                              + (uint32_t)((((2 * ks) + lhi) ^ am7) * 16);
                ldsm4(af[i][0], af[i][1], af[i][2], af[i][3], addr);
            }
            #pragma unroll
            for (int jp = 0; jp < 2; ++jp) {
                uint32_t addr = bsb + (uint32_t)((wn + 16 * jp + lrow) * 128)
                              + (uint32_t)((((2 * ks) + lhi) ^ bn7) * 16);
                ldsm4(bf[2 * jp][0], bf[2 * jp + 1][0],
                      bf[2 * jp][1], bf[2 * jp + 1][1], addr);
            }
            #pragma unroll
            for (int i = 0; i < 4; ++i)
                #pragma unroll
                for (int j = 0; j < 4; ++j)
                    mma_tf32(acc[i][j], af[i][0], af[i][1], af[i][2], af[i][3],
                             bf[j][0], bf[j][1]);
        }
        __syncthreads();   // buffer cur may be overwritten next iteration
    }

    // epilogue
    #pragma unroll
    for (int i = 0; i < 4; ++i) {
        #pragma unroll
        for (int j = 0; j < 4; ++j) {
            const int row = gm + wm + 16 * i + g;
            const int col = gn + wn + 8 * j + 2 * r;
            float2 v0 = make_float2(acc[i][j][0], acc[i][j][1]);
            float2 v1 = make_float2(acc[i][j][2], acc[i][j][3]);
            if (resid) {
                float2 r0 = *(const float2*)&resid[(size_t)row * DMODEL + col];
                float2 r1 = *(const float2*)&resid[(size_t)(row + 8) * DMODEL + col];
                v0.x += r0.x; v0.y += r0.y;
                v1.x += r1.x; v1.y += r1.y;
            }
            *(float2*)&C[(size_t)row * DMODEL + col]       = v0;
            *(float2*)&C[(size_t)(row + 8) * DMODEL + col] = v1;
        }
    }
}

__global__ __launch_bounds__(256, 2) void gemm_qkv_kernel()
{
    const int mat = blockIdx.x >> 3;
    const float* Bt = (mat == 0) ? g_wqt : (mat == 1) ? g_wkt : g_wvt;
    float* C = (mat == 0) ? g_q : (mat == 1) ? g_k : g_v;
    gemm_body(g_ha, Bt, C, nullptr, blockIdx.y, blockIdx.x & 7);
}

__global__ __launch_bounds__(256, 2) void gemm_out_kernel(float* __restrict__ out)
{
    gemm_body(g_ctx, g_wot, out, g_h, blockIdx.y, blockIdx.x);
}

// ---------------------------------------------------------------------------
// Attention: one block per (b, h). scores 28x28 + teeth bias, softmax, ctx.
// ctx written tf32-rounded (it only feeds the out-projection GEMM).
// ---------------------------------------------------------------------------
__global__ __launch_bounds__(256) void attn_kernel()
{
    const int h = blockIdx.x;
    const int b = blockIdx.y;
    __shared__ float sq[SEQ][65], sk[SEQ][65], sv[SEQ][65];
    __shared__ float sp[SEQ][29];

    const int tid = threadIdx.x;
    const size_t base = (size_t)b * SEQ * DMODEL + (size_t)h * DHEAD;

    for (int idx = tid; idx < SEQ * (DHEAD / 4); idx += 256) {
        const int row = idx >> 4;            // 0..27
        const int c   = (idx & 15) * 4;      // 0..60
        const size_t gofs = base + (size_t)row * DMODEL + c;
        float4 qv = *(const float4*)(g_q + gofs);
        float4 kv = *(const float4*)(g_k + gofs);
        float4 vv = *(const float4*)(g_v + gofs);
        sq[row][c] = qv.x; sq[row][c + 1] = qv.y; sq[row][c + 2] = qv.z; sq[row][c + 3] = qv.w;
        sk[row][c] = kv.x; sk[row][c + 1] = kv.y; sk[row][c + 2] = kv.z; sk[row][c + 3] = kv.w;
        sv[row][c] = vv.x; sv[row][c + 1] = vv.y; sv[row][c + 2] = vv.z; sv[row][c + 3] = vv.w;
    }
    __syncthreads();

    const float slope = exp2f(-0.5f * (float)(h + 1));

    for (int e = tid; e < SEQ * SEQ; e += 256) {
        const int i = e / SEQ;
        const int j = e - i * SEQ;
        float acc = 0.f;
        #pragma unroll
        for (int d = 0; d < DHEAD; ++d) acc += sq[i][d] * sk[j][d];
        int dc = (i % 14) - (j % 14); if (dc < 0) dc = -dc;
        int dr = (i / 14) - (j / 14); if (dr < 0) dr = -dr;
        sp[i][j] = acc + slope * (float)(dc + dr);
    }
    __syncthreads();

    if (tid < SEQ) {
        float m = -1e30f;
        #pragma unroll
        for (int j = 0; j < SEQ; ++j) m = fmaxf(m, sp[tid][j]);
        float s = 0.f;
        float e[SEQ];
        #pragma unroll
        for (int j = 0; j < SEQ; ++j) { e[j] = __expf(sp[tid][j] - m); s += e[j]; }
        const float inv = 1.0f / s;
        #pragma unroll
        for (int j = 0; j < SEQ; ++j) sp[tid][j] = e[j] * inv;
    }
    __syncthreads();

    for (int e = tid; e < SEQ * DHEAD; e += 256) {
        const int i = e >> 6;
        const int d = e & 63;
        float acc = 0.f;
        #pragma unroll
        for (int j = 0; j < SEQ; ++j) acc += sp[i][j] * sv[j][d];
        g_ctx[base + (size_t)i * DMODEL + d] = __uint_as_float(f2tf(acc));
    }
}

// ---------------------------------------------------------------------------
// Launch
// ---------------------------------------------------------------------------
extern "C" void kernel_launch(void* const* d_in, const int* in_sizes, int n_in,
                              void* d_out, int out_size)
{
    const float* hidden = (const float*)d_in[0];
    const float* wq     = (const float*)d_in[1];
    const float* wk     = (const float*)d_in[2];
    const float* wv     = (const float*)d_in[3];
    const float* wo     = (const float*)d_in[4];
    const float* gamma  = (const float*)d_in[5];
    const float* beta   = (const float*)d_in[6];
    float* out = (float*)d_out;

    // 64KB dynamic smem for the GEMMs. Unconditional every launch (idempotent,
    // host-side, capture-legal) — no static guards per harness rules.
    cudaFuncSetAttribute(gemm_qkv_kernel,
                         cudaFuncAttributeMaxDynamicSharedMemorySize, SMEM_BYTES);
    cudaFuncSetAttribute(gemm_out_kernel,
                         cudaFuncAttributeMaxDynamicSharedMemorySize, SMEM_BYTES);

    prep_weights_kernel<<<dim3(32, 32, 4), dim3(32, 8)>>>(wq, wk, wv, wo);
    ln_kernel<<<RROWS, 256>>>(hidden, gamma, beta);
    gemm_qkv_kernel<<<dim3(24, RROWS / BM), 256, SMEM_BYTES>>>();
    attn_kernel<<<dim3(NHEAD, BATCH), 256>>>();
    gemm_out_kernel<<<dim3(8, RROWS / BM), 256, SMEM_BYTES>>>(out);
}

// round 16
// speedup vs baseline: 2.0030x; 1.0576x over previous
#include <cuda_runtime.h>
#include <cuda_bf16.h>
#include <cstdint>

// Problem constants
#define BATCH   2048
#define SEQ     28
#define DMODEL  1024
#define NHEAD   16
#define DHEAD   64
#define RROWS   (BATCH * SEQ)          // 57344
#define RC      (RROWS * DMODEL)       // 58,720,256 elements

// Scratch (device globals: allocation-free rule)
__device__ float g_h  [RC];            // exact LN output (residual source)
__device__ float g_ha [RC];            // tf32-rounded LN output (GEMM A)
__device__ float g_q  [RC];
__device__ float g_k  [RC];
__device__ float g_v  [RC];
__device__ float g_ctx[RC];            // tf32-rounded ctx (GEMM A)
// tf32-rounded, transposed weights: wt[n][k]
__device__ float g_wqt[DMODEL * DMODEL];
__device__ float g_wkt[DMODEL * DMODEL];
__device__ float g_wvt[DMODEL * DMODEL];
__device__ float g_wot[DMODEL * DMODEL];

__device__ __forceinline__ unsigned f2tf(float x)
{
    unsigned u;
    asm("cvt.rna.tf32.f32 %0, %1;" : "=r"(u) : "f"(x));
    return u;
}

// ---------------------------------------------------------------------------
// Weight prep: transpose + tf32-round. w[k][n] -> wt[n][k]. grid (32,32,4), block (32,8)
// ---------------------------------------------------------------------------
__global__ __launch_bounds__(256) void prep_weights_kernel(const float* __restrict__ wq,
                                                           const float* __restrict__ wk,
                                                           const float* __restrict__ wv,
                                                           const float* __restrict__ wo)
{
    __shared__ float t[32][33];
    const int mat = blockIdx.z;
    const float* src = (mat == 0) ? wq : (mat == 1) ? wk : (mat == 2) ? wv : wo;
    float* dst = (mat == 0) ? g_wqt : (mat == 1) ? g_wkt : (mat == 2) ? g_wvt : g_wot;
    const int n0 = blockIdx.x * 32, k0 = blockIdx.y * 32;
    const int tx = threadIdx.x, ty = threadIdx.y;
    #pragma unroll
    for (int i = 0; i < 4; ++i)
        t[ty + 8 * i][tx] = src[(size_t)(k0 + ty + 8 * i) * DMODEL + n0 + tx];
    __syncthreads();
    #pragma unroll
    for (int i = 0; i < 4; ++i)
        dst[(size_t)(n0 + ty + 8 * i) * DMODEL + k0 + tx] =
            __uint_as_float(f2tf(t[tx][ty + 8 * i]));
}

// ---------------------------------------------------------------------------
// LayerNorm: one block per row of 1024. Writes exact g_h and rounded g_ha.
// ---------------------------------------------------------------------------
__global__ __launch_bounds__(256) void ln_kernel(const float* __restrict__ x,
                                                 const float* __restrict__ gamma,
                                                 const float* __restrict__ beta)
{
    int row = blockIdx.x;
    int tid = threadIdx.x;
    const float4* xr = (const float4*)(x + (size_t)row * DMODEL);
    float4 v = xr[tid];

    float s = v.x + v.y + v.z + v.w;
    float q = v.x * v.x + v.y * v.y + v.z * v.z + v.w * v.w;
    #pragma unroll
    for (int o = 16; o; o >>= 1) {
        s += __shfl_xor_sync(0xffffffffu, s, o);
        q += __shfl_xor_sync(0xffffffffu, q, o);
    }
    __shared__ float ss[8], sq[8];
    int wid = tid >> 5, lane = tid & 31;
    if (lane == 0) { ss[wid] = s; sq[wid] = q; }
    __syncthreads();
    __shared__ float s_mean, s_rstd;
    if (tid == 0) {
        float S = 0.f, Q = 0.f;
        #pragma unroll
        for (int i = 0; i < 8; ++i) { S += ss[i]; Q += sq[i]; }
        float mean = S * (1.0f / DMODEL);
        float var  = Q * (1.0f / DMODEL) - mean * mean;
        s_mean = mean;
        s_rstd = rsqrtf(var + 1e-5f);
    }
    __syncthreads();
    float mean = s_mean, rstd = s_rstd;

    float4 gv = ((const float4*)gamma)[tid];
    float4 bv = ((const float4*)beta)[tid];
    float4 o;
    o.x = (v.x - mean) * rstd * gv.x + bv.x;
    o.y = (v.y - mean) * rstd * gv.y + bv.y;
    o.z = (v.z - mean) * rstd * gv.z + bv.z;
    o.w = (v.w - mean) * rstd * gv.w + bv.w;
    ((float4*)(g_h + (size_t)row * DMODEL))[tid] = o;
    float4 oa;
    oa.x = __uint_as_float(f2tf(o.x));
    oa.y = __uint_as_float(f2tf(o.y));
    oa.z = __uint_as_float(f2tf(o.z));
    oa.w = __uint_as_float(f2tf(o.w));
    ((float4*)(g_ha + (size_t)row * DMODEL))[tid] = oa;
}

// ---------------------------------------------------------------------------
// Shared mma/ldsm helpers
// ---------------------------------------------------------------------------
__device__ __forceinline__ void mma_tf32(float c[4],
                                         unsigned a0, unsigned a1, unsigned a2, unsigned a3,
                                         unsigned b0, unsigned b1)
{
    asm volatile(
        "mma.sync.aligned.m16n8k8.row.col.f32.tf32.tf32.f32 "
        "{%0,%1,%2,%3}, {%4,%5,%6,%7}, {%8,%9}, {%0,%1,%2,%3};"
        : "+f"(c[0]), "+f"(c[1]), "+f"(c[2]), "+f"(c[3])
        : "r"(a0), "r"(a1), "r"(a2), "r"(a3), "r"(b0), "r"(b1));
}

__device__ __forceinline__ void ldsm4(unsigned& r0, unsigned& r1, unsigned& r2, unsigned& r3,
                                      uint32_t addr)
{
    asm volatile("ldmatrix.sync.aligned.m8n8.x4.shared.b16 {%0,%1,%2,%3}, [%4];"
                 : "=r"(r0), "=r"(r1), "=r"(r2), "=r"(r3) : "r"(addr));
}

__device__ __forceinline__ void cp16(uint32_t dst, const float* src)
{
    asm volatile("cp.async.cg.shared.global [%0], [%1], 16;" :: "r"(dst), "l"(src));
}

// ---------------------------------------------------------------------------
// TF32 GEMM: C[57344 x 1024] = A[57344 x 1024] * Bt^T (+ resid)
// cp.async staging, double-buffered, ldmatrix fragments. (Unchanged from R11 win.)
// ---------------------------------------------------------------------------
#define BM 128
#define BN 128
#define BK 32
#define ABYTES (BM * BK * 4)            // 16 KB per buffer
#define SMEM_BYTES (4 * ABYTES)         // 64 KB total

__device__ __forceinline__ void gemm_body(const float* __restrict__ A,
                                          const float* __restrict__ Bt,
                                          float* __restrict__ C,
                                          const float* __restrict__ resid,
                                          int mt, int nt)
{
    extern __shared__ unsigned sm[];

    const int tid  = threadIdx.x;
    const int wid  = tid >> 5;
    const int lane = tid & 31;
    const int wm   = (wid & 1) * 64;
    const int wn   = (wid >> 1) * 32;
    const int g    = lane >> 2;
    const int r    = lane & 3;

    const int gm = mt * BM;
    const int gn = nt * BN;

    const int s_row   = tid >> 3;
    const int s_k     = (tid & 7) * 4;
    const int s_chunk = (tid & 7) ^ (s_row & 7);

    const uint32_t smBase  = (uint32_t)__cvta_generic_to_shared(sm);
    const uint32_t asBase0 = smBase;
    const uint32_t bsBase0 = smBase + 2 * ABYTES;

    const int lrow = lane & 15;
    const int lhi  = lane >> 4;
    const int am7  = (wm + lrow) & 7;
    const int bn7  = (wn + lrow) & 7;

    const float* Ap = A  + (size_t)(gm + s_row) * DMODEL + s_k;
    const float* Bp = Bt + (size_t)(gn + s_row) * DMODEL + s_k;
    const uint32_t dstOff = (uint32_t)(s_row * 128 + s_chunk * 16);

    const int KT = DMODEL / BK;

    {
        #pragma unroll
        for (int it = 0; it < 4; ++it) {
            cp16(asBase0 + dstOff + (uint32_t)(32 * it) * 128, Ap + (size_t)(32 * it) * DMODEL);
            cp16(bsBase0 + dstOff + (uint32_t)(32 * it) * 128, Bp + (size_t)(32 * it) * DMODEL);
        }
        asm volatile("cp.async.commit_group;");
    }

    float acc[4][4][4];
    #pragma unroll
    for (int i = 0; i < 4; ++i)
        #pragma unroll
        for (int j = 0; j < 4; ++j)
            #pragma unroll
            for (int t = 0; t < 4; ++t) acc[i][j][t] = 0.f;

    for (int kt = 0; kt < KT; ++kt) {
        const int cur = kt & 1;

        if (kt < KT - 1) {
            const uint32_t an = asBase0 + (uint32_t)(cur ^ 1) * ABYTES + dstOff;
            const uint32_t bn = bsBase0 + (uint32_t)(cur ^ 1) * ABYTES + dstOff;
            const float* An = Ap + (size_t)(kt + 1) * BK;
            const float* Bn = Bp + (size_t)(kt + 1) * BK;
            #pragma unroll
            for (int it = 0; it < 4; ++it) {
                cp16(an + (uint32_t)(32 * it) * 128, An + (size_t)(32 * it) * DMODEL);
                cp16(bn + (uint32_t)(32 * it) * 128, Bn + (size_t)(32 * it) * DMODEL);
            }
            asm volatile("cp.async.commit_group;");
            asm volatile("cp.async.wait_group 1;" ::: "memory");
        } else {
            asm volatile("cp.async.wait_group 0;" ::: "memory");
        }
        __syncthreads();

        const uint32_t asb = asBase0 + (uint32_t)cur * ABYTES;
        const uint32_t bsb = bsBase0 + (uint32_t)cur * ABYTES;

        #pragma unroll
        for (int ks = 0; ks < 4; ++ks) {
            unsigned af[4][4], bf[4][2];
            #pragma unroll
            for (int i = 0; i < 4; ++i) {
                uint32_t addr = asb + (uint32_t)((wm + 16 * i + lrow) * 128)
                              + (uint32_t)((((2 * ks) + lhi) ^ am7) * 16);
                ldsm4(af[i][0], af[i][1], af[i][2], af[i][3], addr);
            }
            #pragma unroll
            for (int jp = 0; jp < 2; ++jp) {
                uint32_t addr = bsb + (uint32_t)((wn + 16 * jp + lrow) * 128)
                              + (uint32_t)((((2 * ks) + lhi) ^ bn7) * 16);
                ldsm4(bf[2 * jp][0], bf[2 * jp + 1][0],
                      bf[2 * jp][1], bf[2 * jp + 1][1], addr);
            }
            #pragma unroll
            for (int i = 0; i < 4; ++i)
                #pragma unroll
                for (int j = 0; j < 4; ++j)
                    mma_tf32(acc[i][j], af[i][0], af[i][1], af[i][2], af[i][3],
                             bf[j][0], bf[j][1]);
        }
        __syncthreads();
    }

    #pragma unroll
    for (int i = 0; i < 4; ++i) {
        #pragma unroll
        for (int j = 0; j < 4; ++j) {
            const int row = gm + wm + 16 * i + g;
            const int col = gn + wn + 8 * j + 2 * r;
            float2 v0 = make_float2(acc[i][j][0], acc[i][j][1]);
            float2 v1 = make_float2(acc[i][j][2], acc[i][j][3]);
            if (resid) {
                float2 r0 = *(const float2*)&resid[(size_t)row * DMODEL + col];
                float2 r1 = *(const float2*)&resid[(size_t)(row + 8) * DMODEL + col];
                v0.x += r0.x; v0.y += r0.y;
                v1.x += r1.x; v1.y += r1.y;
            }
            *(float2*)&C[(size_t)row * DMODEL + col]       = v0;
            *(float2*)&C[(size_t)(row + 8) * DMODEL + col] = v1;
        }
    }
}

__global__ __launch_bounds__(256, 2) void gemm_qkv_kernel()
{
    const int mat = blockIdx.x >> 3;
    const float* Bt = (mat == 0) ? g_wqt : (mat == 1) ? g_wkt : g_wvt;
    float* C = (mat == 0) ? g_q : (mat == 1) ? g_k : g_v;
    gemm_body(g_ha, Bt, C, nullptr, blockIdx.y, blockIdx.x & 7);
}

__global__ __launch_bounds__(256, 2) void gemm_out_kernel(float* __restrict__ out)
{
    gemm_body(g_ctx, g_wot, out, g_h, blockIdx.y, blockIdx.x);
}

// ---------------------------------------------------------------------------
// Tensor-core attention: one block per (b, h). tf32x3 (hi/lo) MMA.
// S = Q*K^T (28->32 padded), softmax+teeth bias, ctx = P*V.
// All B-operand fragments loaded via the GEMM-validated ldsm4 pattern
// (16-row span, four 8x8 matrices: {rows0-7,rows8-15} x {k-lo,k-hi}).
// smem float layout (dynamic, 56KB):
//   QH 0, QL 2048, KH 4096, KL 6144, VH 8192, VL 10240, PH 12288, PL 13312
// ---------------------------------------------------------------------------
#define QH_F 0
#define QL_F 2048
#define KH_F 4096
#define KL_F 6144
#define VH_F 8192
#define VL_F 10240
#define PH_F 12288
#define PL_F 13312
#define ATTN_SMEM_BYTES (14336 * 4)

__device__ __forceinline__ int phidx(int i, int j)
{
    return PH_F + i * 32 + (((j >> 2) ^ (i & 7)) << 2) + (j & 3);
}

__global__ __launch_bounds__(256) void attn_kernel()
{
    extern __shared__ float smf[];
    const int h = blockIdx.x;
    const int b = blockIdx.y;
    const int tid  = threadIdx.x;
    const int wid  = tid >> 5;
    const int lane = tid & 31;
    const int g    = lane >> 2;
    const int r    = lane & 3;
    const int lrow = lane & 15;
    const int lhi  = lane >> 4;

    const size_t base = (size_t)b * SEQ * DMODEL + (size_t)h * DHEAD;
    const uint32_t smB = (uint32_t)__cvta_generic_to_shared(smf);

    // ---- load Q,K into swizzled hi/lo tiles (pad rows 28..31 = 0) ----
    for (int idx = tid; idx < 32 * 16; idx += 256) {
        const int row = idx >> 4;
        const int c4  = idx & 15;          // 16B chunk within 64-float row
        const int kc  = c4 >> 3;
        const int c   = c4 & 7;
        float4 qv = make_float4(0.f, 0.f, 0.f, 0.f), kv = qv;
        if (row < SEQ) {
            qv = *(const float4*)(g_q + base + (size_t)row * DMODEL + c4 * 4);
            kv = *(const float4*)(g_k + base + (size_t)row * DMODEL + c4 * 4);
        }
        const int o = kc * 1024 + row * 32 + ((c ^ (row & 7)) << 2);
        float4 hi, lo;
        hi.x = __uint_as_float(f2tf(qv.x)); lo.x = __uint_as_float(f2tf(qv.x - hi.x));
        hi.y = __uint_as_float(f2tf(qv.y)); lo.y = __uint_as_float(f2tf(qv.y - hi.y));
        hi.z = __uint_as_float(f2tf(qv.z)); lo.z = __uint_as_float(f2tf(qv.z - hi.z));
        hi.w = __uint_as_float(f2tf(qv.w)); lo.w = __uint_as_float(f2tf(qv.w - hi.w));
        *(float4*)&smf[QH_F + o] = hi;
        *(float4*)&smf[QL_F + o] = lo;
        hi.x = __uint_as_float(f2tf(kv.x)); lo.x = __uint_as_float(f2tf(kv.x - hi.x));
        hi.y = __uint_as_float(f2tf(kv.y)); lo.y = __uint_as_float(f2tf(kv.y - hi.y));
        hi.z = __uint_as_float(f2tf(kv.z)); lo.z = __uint_as_float(f2tf(kv.z - hi.z));
        hi.w = __uint_as_float(f2tf(kv.w)); lo.w = __uint_as_float(f2tf(kv.w - hi.w));
        *(float4*)&smf[KH_F + o] = hi;
        *(float4*)&smf[KL_F + o] = lo;
    }

    // ---- load V transposed: Vt[d][j], hi/lo ----
    for (int idx = tid; idx < SEQ * 16; idx += 256) {
        const int j  = idx >> 4;
        const int c4 = idx & 15;
        float4 vv = *(const float4*)(g_v + base + (size_t)j * DMODEL + c4 * 4);
        const float ve[4] = { vv.x, vv.y, vv.z, vv.w };
        #pragma unroll
        for (int e = 0; e < 4; ++e) {
            const int d = c4 * 4 + e;
            const int o = d * 32 + (((j >> 2) ^ (d & 7)) << 2) + (j & 3);
            float hi = __uint_as_float(f2tf(ve[e]));
            smf[VH_F + o] = hi;
            smf[VL_F + o] = __uint_as_float(f2tf(ve[e] - hi));
        }
    }
    // zero Vt pad cols j=28..31 (all 64 d rows)
    for (int idx = tid; idx < 64 * 4; idx += 256) {
        const int d = idx >> 2;
        const int j = 28 + (idx & 3);
        const int o = d * 32 + (((j >> 2) ^ (d & 7)) << 2) + (j & 3);
        smf[VH_F + o] = 0.f;
        smf[VL_F + o] = 0.f;
    }
    __syncthreads();

    // ---- phase 1: S = Q*K^T. warp w: mt = w&1 (m16), nt = w>>1 (n8 of 32) ----
    const int mt  = wid & 1;
    const int nt  = wid >> 1;          // 0..3
    const int ntp = nt >> 1;           // 0..1 : which 16-row K span
    const int sel = nt & 1;            // which 8-row half of the span
    const int arow  = 16 * mt + lrow;
    const int a7    = arow & 7;
    const int brow1 = 16 * ntp + lrow; // GEMM-validated 16-row B pattern
    const int b71   = brow1 & 7;

    float sacc[4] = {0.f, 0.f, 0.f, 0.f};
    #pragma unroll
    for (int kc = 0; kc < 2; ++kc) {
        #pragma unroll
        for (int ks = 0; ks < 4; ++ks) {
            const uint32_t aoff = (uint32_t)(kc * 4096 + arow * 128
                                 + ((((2 * ks) + lhi) ^ a7) << 4));
            unsigned ah[4], al[4];
            ldsm4(ah[0], ah[1], ah[2], ah[3], smB + QH_F * 4 + aoff);
            ldsm4(al[0], al[1], al[2], al[3], smB + QL_F * 4 + aoff);
            const uint32_t boff = (uint32_t)(kc * 4096 + brow1 * 128
                                 + ((((2 * ks) + lhi) ^ b71) << 4));
            // m0=rows0-7/klo, m1=rows8-15/klo, m2=rows0-7/khi, m3=rows8-15/khi
            unsigned kh[4], kl[4];
            ldsm4(kh[0], kh[1], kh[2], kh[3], smB + KH_F * 4 + boff);
            ldsm4(kl[0], kl[1], kl[2], kl[3], smB + KL_F * 4 + boff);
            const unsigned bh0 = sel ? kh[1] : kh[0];
            const unsigned bh1 = sel ? kh[3] : kh[2];
            const unsigned bl0 = sel ? kl[1] : kl[0];
            const unsigned bl1 = sel ? kl[3] : kl[2];
            mma_tf32(sacc, ah[0], ah[1], ah[2], ah[3], bh0, bh1);
            mma_tf32(sacc, ah[0], ah[1], ah[2], ah[3], bl0, bl1);
            mma_tf32(sacc, al[0], al[1], al[2], al[3], bh0, bh1);
        }
    }
    // store raw S to PH
    {
        const int i0 = 16 * mt + g;
        const int j0 = 8 * nt + 2 * r;
        smf[phidx(i0,     j0)]     = sacc[0];
        smf[phidx(i0,     j0 + 1)] = sacc[1];
        smf[phidx(i0 + 8, j0)]     = sacc[2];
        smf[phidx(i0 + 8, j0 + 1)] = sacc[3];
    }
    __syncthreads();

    // zero PL entirely (pad cols/rows must be 0, not NaN)
    for (int z = tid; z < 1024; z += 256) smf[PL_F + z] = 0.f;
    __syncthreads();

    // ---- softmax with teeth bias (rows i<28) ----
    if (tid < SEQ) {
        const int i = tid;
        const float slope = exp2f(-0.5f * (float)(h + 1));
        const int ic = i % 14, ir = i / 14;
        float e[SEQ];
        float m = -1e30f;
        #pragma unroll
        for (int j = 0; j < SEQ; ++j) {
            int dc = ic - (j % 14); if (dc < 0) dc = -dc;
            int dr = ir - (j / 14); if (dr < 0) dr = -dr;
            float s = smf[phidx(i, j)] + slope * (float)(dc + dr);
            e[j] = s;
            m = fmaxf(m, s);
        }
        float sum = 0.f;
        #pragma unroll
        for (int j = 0; j < SEQ; ++j) { e[j] = __expf(e[j] - m); sum += e[j]; }
        const float inv = 1.0f / sum;
        #pragma unroll
        for (int j = 0; j < SEQ; ++j) {
            float p  = e[j] * inv;
            float ph = __uint_as_float(f2tf(p));
            smf[phidx(i, j)]        = ph;
            smf[phidx(i, j) + 1024] = __uint_as_float(f2tf(p - ph));
        }
        // pad cols 28..31 of PH stay 0 (K pad rows were zeroed -> S pad = 0)
    }
    __syncthreads();

    // ---- phase 2: ctx = P * V. warp w -> mt = w&1, n-tiles {2*(w>>1), +1} ----
    const int brow2 = 16 * (wid >> 1) + lrow;   // 16-row Vt span (GEMM pattern)
    const int b72   = brow2 & 7;
    float cacc[2][4];
    #pragma unroll
    for (int t = 0; t < 2; ++t)
        #pragma unroll
        for (int q = 0; q < 4; ++q) cacc[t][q] = 0.f;

    #pragma unroll
    for (int ks = 0; ks < 4; ++ks) {
        const uint32_t aoff = (uint32_t)(arow * 128 + ((((2 * ks) + lhi) ^ a7) << 4));
        unsigned ah[4], al[4];
        ldsm4(ah[0], ah[1], ah[2], ah[3], smB + PH_F * 4 + aoff);
        ldsm4(al[0], al[1], al[2], al[3], smB + PL_F * 4 + aoff);
        const uint32_t boff = (uint32_t)(brow2 * 128 + ((((2 * ks) + lhi) ^ b72) << 4));
        unsigned vh[4], vl[4];
        ldsm4(vh[0], vh[1], vh[2], vh[3], smB + VH_F * 4 + boff);
        ldsm4(vl[0], vl[1], vl[2], vl[3], smB + VL_F * 4 + boff);
        // tile t: b0 = m(t)/klo, b1 = m(t)/khi  (t=0: rows0-7 -> m0,m2; t=1: m1,m3)
        #pragma unroll
        for (int t = 0; t < 2; ++t) {
            mma_tf32(cacc[t], ah[0], ah[1], ah[2], ah[3], vh[t], vh[t + 2]);
            mma_tf32(cacc[t], ah[0], ah[1], ah[2], ah[3], vl[t], vl[t + 2]);
            mma_tf32(cacc[t], al[0], al[1], al[2], al[3], vh[t], vh[t + 2]);
        }
    }

    // ---- write ctx (tf32-rounded; rows < 28 only) ----
    {
        const int i0 = 16 * mt + g;          // always < 28
        #pragma unroll
        for (int t = 0; t < 2; ++t) {
            const int col = 8 * (2 * (wid >> 1) + t) + 2 * r;
            float2 v0;
            v0.x = __uint_as_float(f2tf(cacc[t][0]));
            v0.y = __uint_as_float(f2tf(cacc[t][1]));
            *(float2*)&g_ctx[base + (size_t)i0 * DMODEL + col] = v0;
            if (i0 + 8 < SEQ) {
                float2 v1;
                v1.x = __uint_as_float(f2tf(cacc[t][2]));
                v1.y = __uint_as_float(f2tf(cacc[t][3]));
                *(float2*)&g_ctx[base + (size_t)(i0 + 8) * DMODEL + col] = v1;
            }
        }
    }
}

// ---------------------------------------------------------------------------
// Launch
// ---------------------------------------------------------------------------
extern "C" void kernel_launch(void* const* d_in, const int* in_sizes, int n_in,
                              void* d_out, int out_size)
{
    const float* hidden = (const float*)d_in[0];
    const float* wq     = (const float*)d_in[1];
    const float* wk     = (const float*)d_in[2];
    const float* wv     = (const float*)d_in[3];
    const float* wo     = (const float*)d_in[4];
    const float* gamma  = (const float*)d_in[5];
    const float* beta   = (const float*)d_in[6];
    float* out = (float*)d_out;

    // Dynamic smem opt-ins. Unconditional every launch (idempotent, host-side,
    // capture-legal) — no static guards per harness rules.
    cudaFuncSetAttribute(gemm_qkv_kernel,
                         cudaFuncAttributeMaxDynamicSharedMemorySize, SMEM_BYTES);
    cudaFuncSetAttribute(gemm_out_kernel,
                         cudaFuncAttributeMaxDynamicSharedMemorySize, SMEM_BYTES);
    cudaFuncSetAttribute(attn_kernel,
                         cudaFuncAttributeMaxDynamicSharedMemorySize, ATTN_SMEM_BYTES);

    prep_weights_kernel<<<dim3(32, 32, 4), dim3(32, 8)>>>(wq, wk, wv, wo);
    ln_kernel<<<RROWS, 256>>>(hidden, gamma, beta);
    gemm_qkv_kernel<<<dim3(24, RROWS / BM), 256, SMEM_BYTES>>>();
    attn_kernel<<<dim3(NHEAD, BATCH), 256, ATTN_SMEM_BYTES>>>();
    gemm_out_kernel<<<dim3(8, RROWS / BM), 256, SMEM_BYTES>>>(out);
}

// round 17
// speedup vs baseline: 2.0493x; 1.0231x over previous
#include <cuda_runtime.h>
#include <cuda_bf16.h>
#include <cstdint>

// Problem constants
#define BATCH   2048
#define SEQ     28
#define DMODEL  1024
#define NHEAD   16
#define DHEAD   64
#define RROWS   (BATCH * SEQ)          // 57344
#define RC      (RROWS * DMODEL)       // 58,720,256 elements

// Scratch (device globals: allocation-free rule)
__device__ float g_h  [RC];            // exact LN output (residual source)
__device__ float g_ha [RC];            // tf32-rounded LN output (GEMM A)
__device__ float g_q  [RC];
__device__ float g_k  [RC];
__device__ float g_v  [RC];
__device__ float g_ctx[RC];            // tf32-rounded ctx (GEMM A)
// tf32-rounded, transposed weights: wt[n][k]
__device__ float g_wqt[DMODEL * DMODEL];
__device__ float g_wkt[DMODEL * DMODEL];
__device__ float g_wvt[DMODEL * DMODEL];
__device__ float g_wot[DMODEL * DMODEL];

__device__ __forceinline__ unsigned f2tf(float x)
{
    unsigned u;
    asm("cvt.rna.tf32.f32 %0, %1;" : "=r"(u) : "f"(x));
    return u;
}

// ---------------------------------------------------------------------------
// Weight prep: transpose + tf32-round. w[k][n] -> wt[n][k]. grid (32,32,4), block (32,8)
// ---------------------------------------------------------------------------
__global__ __launch_bounds__(256) void prep_weights_kernel(const float* __restrict__ wq,
                                                           const float* __restrict__ wk,
                                                           const float* __restrict__ wv,
                                                           const float* __restrict__ wo)
{
    __shared__ float t[32][33];
    const int mat = blockIdx.z;
    const float* src = (mat == 0) ? wq : (mat == 1) ? wk : (mat == 2) ? wv : wo;
    float* dst = (mat == 0) ? g_wqt : (mat == 1) ? g_wkt : (mat == 2) ? g_wvt : g_wot;
    const int n0 = blockIdx.x * 32, k0 = blockIdx.y * 32;
    const int tx = threadIdx.x, ty = threadIdx.y;
    #pragma unroll
    for (int i = 0; i < 4; ++i)
        t[ty + 8 * i][tx] = src[(size_t)(k0 + ty + 8 * i) * DMODEL + n0 + tx];
    __syncthreads();
    #pragma unroll
    for (int i = 0; i < 4; ++i)
        dst[(size_t)(n0 + ty + 8 * i) * DMODEL + k0 + tx] =
            __uint_as_float(f2tf(t[tx][ty + 8 * i]));
}

// ---------------------------------------------------------------------------
// LayerNorm: one block per row of 1024. Writes exact g_h and rounded g_ha.
// ---------------------------------------------------------------------------
__global__ __launch_bounds__(256) void ln_kernel(const float* __restrict__ x,
                                                 const float* __restrict__ gamma,
                                                 const float* __restrict__ beta)
{
    int row = blockIdx.x;
    int tid = threadIdx.x;
    const float4* xr = (const float4*)(x + (size_t)row * DMODEL);
    float4 v = xr[tid];

    float s = v.x + v.y + v.z + v.w;
    float q = v.x * v.x + v.y * v.y + v.z * v.z + v.w * v.w;
    #pragma unroll
    for (int o = 16; o; o >>= 1) {
        s += __shfl_xor_sync(0xffffffffu, s, o);
        q += __shfl_xor_sync(0xffffffffu, q, o);
    }
    __shared__ float ss[8], sq[8];
    int wid = tid >> 5, lane = tid & 31;
    if (lane == 0) { ss[wid] = s; sq[wid] = q; }
    __syncthreads();
    __shared__ float s_mean, s_rstd;
    if (tid == 0) {
        float S = 0.f, Q = 0.f;
        #pragma unroll
        for (int i = 0; i < 8; ++i) { S += ss[i]; Q += sq[i]; }
        float mean = S * (1.0f / DMODEL);
        float var  = Q * (1.0f / DMODEL) - mean * mean;
        s_mean = mean;
        s_rstd = rsqrtf(var + 1e-5f);
    }
    __syncthreads();
    float mean = s_mean, rstd = s_rstd;

    float4 gv = ((const float4*)gamma)[tid];
    float4 bv = ((const float4*)beta)[tid];
    float4 o;
    o.x = (v.x - mean) * rstd * gv.x + bv.x;
    o.y = (v.y - mean) * rstd * gv.y + bv.y;
    o.z = (v.z - mean) * rstd * gv.z + bv.z;
    o.w = (v.w - mean) * rstd * gv.w + bv.w;
    ((float4*)(g_h + (size_t)row * DMODEL))[tid] = o;
    float4 oa;
    oa.x = __uint_as_float(f2tf(o.x));
    oa.y = __uint_as_float(f2tf(o.y));
    oa.z = __uint_as_float(f2tf(o.z));
    oa.w = __uint_as_float(f2tf(o.w));
    ((float4*)(g_ha + (size_t)row * DMODEL))[tid] = oa;
}

// ---------------------------------------------------------------------------
// Shared mma/ldsm helpers
// ---------------------------------------------------------------------------
__device__ __forceinline__ void mma_tf32(float c[4],
                                         unsigned a0, unsigned a1, unsigned a2, unsigned a3,
                                         unsigned b0, unsigned b1)
{
    asm volatile(
        "mma.sync.aligned.m16n8k8.row.col.f32.tf32.tf32.f32 "
        "{%0,%1,%2,%3}, {%4,%5,%6,%7}, {%8,%9}, {%0,%1,%2,%3};"
        : "+f"(c[0]), "+f"(c[1]), "+f"(c[2]), "+f"(c[3])
        : "r"(a0), "r"(a1), "r"(a2), "r"(a3), "r"(b0), "r"(b1));
}

__device__ __forceinline__ void ldsm4(unsigned& r0, unsigned& r1, unsigned& r2, unsigned& r3,
                                      uint32_t addr)
{
    asm volatile("ldmatrix.sync.aligned.m8n8.x4.shared.b16 {%0,%1,%2,%3}, [%4];"
                 : "=r"(r0), "=r"(r1), "=r"(r2), "=r"(r3) : "r"(addr));
}

__device__ __forceinline__ void cp16(uint32_t dst, const float* src)
{
    asm volatile("cp.async.cg.shared.global [%0], [%1], 16;" :: "r"(dst), "l"(src));
}

// ---------------------------------------------------------------------------
// TF32 GEMM: C[57344 x 1024] = A[57344 x 1024] * Bt^T (+ resid)
// 3-stage cp.async pipeline, ONE __syncthreads per BK-iter, ldmatrix fragments.
// ---------------------------------------------------------------------------
#define BM 128
#define BN 128
#define BK 32
#define ABYTES (BM * BK * 4)            // 16 KB per buffer
#define SMEM_BYTES (6 * ABYTES)         // 3x(A+B) = 96 KB total

__device__ __forceinline__ void gemm_body(const float* __restrict__ A,
                                          const float* __restrict__ Bt,
                                          float* __restrict__ C,
                                          const float* __restrict__ resid,
                                          int mt, int nt)
{
    extern __shared__ unsigned sm[];

    const int tid  = threadIdx.x;
    const int wid  = tid >> 5;
    const int lane = tid & 31;
    const int wm   = (wid & 1) * 64;
    const int wn   = (wid >> 1) * 32;
    const int g    = lane >> 2;
    const int r    = lane & 3;

    const int gm = mt * BM;
    const int gn = nt * BN;

    const int s_row   = tid >> 3;
    const int s_k     = (tid & 7) * 4;
    const int s_chunk = (tid & 7) ^ (s_row & 7);

    const uint32_t smBase  = (uint32_t)__cvta_generic_to_shared(sm);
    const uint32_t asBase0 = smBase;                    // A bufs 0..2
    const uint32_t bsBase0 = smBase + 3 * ABYTES;       // B bufs 0..2

    const int lrow = lane & 15;
    const int lhi  = lane >> 4;
    const int am7  = (wm + lrow) & 7;
    const int bn7  = (wn + lrow) & 7;

    const float* Ap = A  + (size_t)(gm + s_row) * DMODEL + s_k;
    const float* Bp = Bt + (size_t)(gn + s_row) * DMODEL + s_k;
    const uint32_t dstOff = (uint32_t)(s_row * 128 + s_chunk * 16);

    const int KT = DMODEL / BK;

    auto stage = [&](int kt, int bi) {
        const uint32_t ad = asBase0 + (uint32_t)bi * ABYTES + dstOff;
        const uint32_t bd = bsBase0 + (uint32_t)bi * ABYTES + dstOff;
        const float* An = Ap + (size_t)kt * BK;
        const float* Bn = Bp + (size_t)kt * BK;
        #pragma unroll
        for (int it = 0; it < 4; ++it) {
            cp16(ad + (uint32_t)(32 * it) * 128, An + (size_t)(32 * it) * DMODEL);
            cp16(bd + (uint32_t)(32 * it) * 128, Bn + (size_t)(32 * it) * DMODEL);
        }
        asm volatile("cp.async.commit_group;");
    };

    // prologue: stage tiles 0 and 1
    stage(0, 0);
    stage(1, 1);

    float acc[4][4][4];
    #pragma unroll
    for (int i = 0; i < 4; ++i)
        #pragma unroll
        for (int j = 0; j < 4; ++j)
            #pragma unroll
            for (int t = 0; t < 4; ++t) acc[i][j][t] = 0.f;

    int cur = 0, nxt = 2;
    for (int kt = 0; kt < KT; ++kt) {
        if (kt < KT - 1)
            asm volatile("cp.async.wait_group 1;" ::: "memory");
        else
            asm volatile("cp.async.wait_group 0;" ::: "memory");
        // Single barrier: publishes tile kt's async writes AND orders all
        // compute(kt-1) reads of buf (kt-1)%3 == (kt+2)%3 before re-staging it.
        __syncthreads();

        if (kt + 2 < KT) {
            stage(kt + 2, nxt);
            if (++nxt == 3) nxt = 0;
        }

        const uint32_t asb = asBase0 + (uint32_t)cur * ABYTES;
        const uint32_t bsb = bsBase0 + (uint32_t)cur * ABYTES;
        if (++cur == 3) cur = 0;

        #pragma unroll
        for (int ks = 0; ks < 4; ++ks) {
            unsigned af[4][4], bf[4][2];
            #pragma unroll
            for (int i = 0; i < 4; ++i) {
                uint32_t addr = asb + (uint32_t)((wm + 16 * i + lrow) * 128)
                              + (uint32_t)((((2 * ks) + lhi) ^ am7) * 16);
                ldsm4(af[i][0], af[i][1], af[i][2], af[i][3], addr);
            }
            #pragma unroll
            for (int jp = 0; jp < 2; ++jp) {
                uint32_t addr = bsb + (uint32_t)((wn + 16 * jp + lrow) * 128)
                              + (uint32_t)((((2 * ks) + lhi) ^ bn7) * 16);
                ldsm4(bf[2 * jp][0], bf[2 * jp + 1][0],
                      bf[2 * jp][1], bf[2 * jp + 1][1], addr);
            }
            #pragma unroll
            for (int i = 0; i < 4; ++i)
                #pragma unroll
                for (int j = 0; j < 4; ++j)
                    mma_tf32(acc[i][j], af[i][0], af[i][1], af[i][2], af[i][3],
                             bf[j][0], bf[j][1]);
        }
    }

    #pragma unroll
    for (int i = 0; i < 4; ++i) {
        #pragma unroll
        for (int j = 0; j < 4; ++j) {
            const int row = gm + wm + 16 * i + g;
            const int col = gn + wn + 8 * j + 2 * r;
            float2 v0 = make_float2(acc[i][j][0], acc[i][j][1]);
            float2 v1 = make_float2(acc[i][j][2], acc[i][j][3]);
            if (resid) {
                float2 r0 = *(const float2*)&resid[(size_t)row * DMODEL + col];
                float2 r1 = *(const float2*)&resid[(size_t)(row + 8) * DMODEL + col];
                v0.x += r0.x; v0.y += r0.y;
                v1.x += r1.x; v1.y += r1.y;
            }
            *(float2*)&C[(size_t)row * DMODEL + col]       = v0;
            *(float2*)&C[(size_t)(row + 8) * DMODEL + col] = v1;
        }
    }
}

__global__ __launch_bounds__(256, 2) void gemm_qkv_kernel()
{
    const int mat = blockIdx.x >> 3;
    const float* Bt = (mat == 0) ? g_wqt : (mat == 1) ? g_wkt : g_wvt;
    float* C = (mat == 0) ? g_q : (mat == 1) ? g_k : g_v;
    gemm_body(g_ha, Bt, C, nullptr, blockIdx.y, blockIdx.x & 7);
}

__global__ __launch_bounds__(256, 2) void gemm_out_kernel(float* __restrict__ out)
{
    gemm_body(g_ctx, g_wot, out, g_h, blockIdx.y, blockIdx.x);
}

// ---------------------------------------------------------------------------
// Tensor-core attention: one block per (b, h). tf32x3 (hi/lo) MMA.
// S = Q*K^T (28->32 padded), softmax+teeth bias, ctx = P*V.
// All B-operand fragments loaded via the GEMM-validated ldsm4 pattern.
// Vt staging vectorized: per-thread (d, 4j) -> two float4 STS, conflict-free.
// smem float layout (dynamic, 56KB):
//   QH 0, QL 2048, KH 4096, KL 6144, VH 8192, VL 10240, PH 12288, PL 13312
// ---------------------------------------------------------------------------
#define QH_F 0
#define QL_F 2048
#define KH_F 4096
#define KL_F 6144
#define VH_F 8192
#define VL_F 10240
#define PH_F 12288
#define PL_F 13312
#define ATTN_SMEM_BYTES (14336 * 4)

__device__ __forceinline__ int phidx(int i, int j)
{
    return PH_F + i * 32 + (((j >> 2) ^ (i & 7)) << 2) + (j & 3);
}

__global__ __launch_bounds__(256) void attn_kernel()
{
    extern __shared__ float smf[];
    const int h = blockIdx.x;
    const int b = blockIdx.y;
    const int tid  = threadIdx.x;
    const int wid  = tid >> 5;
    const int lane = tid & 31;
    const int g    = lane >> 2;
    const int r    = lane & 3;
    const int lrow = lane & 15;
    const int lhi  = lane >> 4;

    const size_t base = (size_t)b * SEQ * DMODEL + (size_t)h * DHEAD;
    const uint32_t smB = (uint32_t)__cvta_generic_to_shared(smf);

    // ---- load Q,K into swizzled hi/lo tiles (pad rows 28..31 = 0) ----
    for (int idx = tid; idx < 32 * 16; idx += 256) {
        const int row = idx >> 4;
        const int c4  = idx & 15;          // 16B chunk within 64-float row
        const int kc  = c4 >> 3;
        const int c   = c4 & 7;
        float4 qv = make_float4(0.f, 0.f, 0.f, 0.f), kv = qv;
        if (row < SEQ) {
            qv = *(const float4*)(g_q + base + (size_t)row * DMODEL + c4 * 4);
            kv = *(const float4*)(g_k + base + (size_t)row * DMODEL + c4 * 4);
        }
        const int o = kc * 1024 + row * 32 + ((c ^ (row & 7)) << 2);
        float4 hi, lo;
        hi.x = __uint_as_float(f2tf(qv.x)); lo.x = __uint_as_float(f2tf(qv.x - hi.x));
        hi.y = __uint_as_float(f2tf(qv.y)); lo.y = __uint_as_float(f2tf(qv.y - hi.y));
        hi.z = __uint_as_float(f2tf(qv.z)); lo.z = __uint_as_float(f2tf(qv.z - hi.z));
        hi.w = __uint_as_float(f2tf(qv.w)); lo.w = __uint_as_float(f2tf(qv.w - hi.w));
        *(float4*)&smf[QH_F + o] = hi;
        *(float4*)&smf[QL_F + o] = lo;
        hi.x = __uint_as_float(f2tf(kv.x)); lo.x = __uint_as_float(f2tf(kv.x - hi.x));
        hi.y = __uint_as_float(f2tf(kv.y)); lo.y = __uint_as_float(f2tf(kv.y - hi.y));
        hi.z = __uint_as_float(f2tf(kv.z)); lo.z = __uint_as_float(f2tf(kv.z - hi.z));
        hi.w = __uint_as_float(f2tf(kv.w)); lo.w = __uint_as_float(f2tf(kv.w - hi.w));
        *(float4*)&smf[KH_F + o] = hi;
        *(float4*)&smf[KL_F + o] = lo;
    }

    // ---- load V transposed: Vt[d][j], hi/lo. Thread: one d, one 4-j group ->
    //      4 contiguous swizzled floats -> float4 stores (conflict-free),
    //      gmem reads coalesced across d. Pads j=28..31 with zeros. ----
    for (int idx = tid; idx < 64 * 8; idx += 256) {
        const int d = idx & 63;
        const int t = idx >> 6;            // j-group 0..7
        float vj[4];
        #pragma unroll
        for (int u = 0; u < 4; ++u) {
            const int j = 4 * t + u;
            vj[u] = (j < SEQ) ? g_v[base + (size_t)j * DMODEL + d] : 0.f;
        }
        const int o = d * 32 + ((t ^ (d & 7)) << 2);
        float4 hi, lo;
        hi.x = __uint_as_float(f2tf(vj[0])); lo.x = __uint_as_float(f2tf(vj[0] - hi.x));
        hi.y = __uint_as_float(f2tf(vj[1])); lo.y = __uint_as_float(f2tf(vj[1] - hi.y));
        hi.z = __uint_as_float(f2tf(vj[2])); lo.z = __uint_as_float(f2tf(vj[2] - hi.z));
        hi.w = __uint_as_float(f2tf(vj[3])); lo.w = __uint_as_float(f2tf(vj[3] - hi.w));
        *(float4*)&smf[VH_F + o] = hi;
        *(float4*)&smf[VL_F + o] = lo;
    }
    __syncthreads();

    // ---- phase 1: S = Q*K^T. warp w: mt = w&1 (m16), nt = w>>1 (n8 of 32) ----
    const int mt  = wid & 1;
    const int nt  = wid >> 1;          // 0..3
    const int ntp = nt >> 1;           // 0..1 : which 16-row K span
    const int sel = nt & 1;            // which 8-row half of the span
    const int arow  = 16 * mt + lrow;
    const int a7    = arow & 7;
    const int brow1 = 16 * ntp + lrow; // GEMM-validated 16-row B pattern
    const int b71   = brow1 & 7;

    float sacc[4] = {0.f, 0.f, 0.f, 0.f};
    #pragma unroll
    for (int kc = 0; kc < 2; ++kc) {
        #pragma unroll
        for (int ks = 0; ks < 4; ++ks) {
            const uint32_t aoff = (uint32_t)(kc * 4096 + arow * 128
                                 + ((((2 * ks) + lhi) ^ a7) << 4));
            unsigned ah[4], al[4];
            ldsm4(ah[0], ah[1], ah[2], ah[3], smB + QH_F * 4 + aoff);
            ldsm4(al[0], al[1], al[2], al[3], smB + QL_F * 4 + aoff);
            const uint32_t boff = (uint32_t)(kc * 4096 + brow1 * 128
                                 + ((((2 * ks) + lhi) ^ b71) << 4));
            // m0=rows0-7/klo, m1=rows8-15/klo, m2=rows0-7/khi, m3=rows8-15/khi
            unsigned kh[4], kl[4];
            ldsm4(kh[0], kh[1], kh[2], kh[3], smB + KH_F * 4 + boff);
            ldsm4(kl[0], kl[1], kl[2], kl[3], smB + KL_F * 4 + boff);
            const unsigned bh0 = sel ? kh[1] : kh[0];
            const unsigned bh1 = sel ? kh[3] : kh[2];
            const unsigned bl0 = sel ? kl[1] : kl[0];
            const unsigned bl1 = sel ? kl[3] : kl[2];
            mma_tf32(sacc, ah[0], ah[1], ah[2], ah[3], bh0, bh1);
            mma_tf32(sacc, ah[0], ah[1], ah[2], ah[3], bl0, bl1);
            mma_tf32(sacc, al[0], al[1], al[2], al[3], bh0, bh1);
        }
    }
    // store raw S to PH
    {
        const int i0 = 16 * mt + g;
        const int j0 = 8 * nt + 2 * r;
        smf[phidx(i0,     j0)]     = sacc[0];
        smf[phidx(i0,     j0 + 1)] = sacc[1];
        smf[phidx(i0 + 8, j0)]     = sacc[2];
        smf[phidx(i0 + 8, j0 + 1)] = sacc[3];
    }
    __syncthreads();

    // zero PL entirely (pad cols/rows must be 0, not NaN)
    for (int z = tid; z < 1024; z += 256) smf[PL_F + z] = 0.f;
    __syncthreads();

    // ---- softmax with teeth bias (rows i<28) ----
    if (tid < SEQ) {
        const int i = tid;
        const float slope = exp2f(-0.5f * (float)(h + 1));
        const int ic = i % 14, ir = i / 14;
        float e[SEQ];
        float m = -1e30f;
        #pragma unroll
        for (int j = 0; j < SEQ; ++j) {
            int dc = ic - (j % 14); if (dc < 0) dc = -dc;
            int dr = ir - (j / 14); if (dr < 0) dr = -dr;
            float s = smf[phidx(i, j)] + slope * (float)(dc + dr);
            e[j] = s;
            m = fmaxf(m, s);
        }
        float sum = 0.f;
        #pragma unroll
        for (int j = 0; j < SEQ; ++j) { e[j] = __expf(e[j] - m); sum += e[j]; }
        const float inv = 1.0f / sum;
        #pragma unroll
        for (int j = 0; j < SEQ; ++j) {
            float p  = e[j] * inv;
            float ph = __uint_as_float(f2tf(p));
            smf[phidx(i, j)]        = ph;
            smf[phidx(i, j) + 1024] = __uint_as_float(f2tf(p - ph));
        }
        // pad cols 28..31 of PH stay 0 (K pad rows were zeroed -> S pad = 0)
    }
    __syncthreads();

    // ---- phase 2: ctx = P * V. warp w -> mt = w&1, n-tiles {2*(w>>1), +1} ----
    const int brow2 = 16 * (wid >> 1) + lrow;   // 16-row Vt span (GEMM pattern)
    const int b72   = brow2 & 7;
    float cacc[2][4];
    #pragma unroll
    for (int t = 0; t < 2; ++t)
        #pragma unroll
        for (int q = 0; q < 4; ++q) cacc[t][q] = 0.f;

    #pragma unroll
    for (int ks = 0; ks < 4; ++ks) {
        const uint32_t aoff = (uint32_t)(arow * 128 + ((((2 * ks) + lhi) ^ a7) << 4));
        unsigned ah[4], al[4];
        ldsm4(ah[0], ah[1], ah[2], ah[3], smB + PH_F * 4 + aoff);
        ldsm4(al[0], al[1], al[2], al[3], smB + PL_F * 4 + aoff);
        const uint32_t boff = (uint32_t)(brow2 * 128 + ((((2 * ks) + lhi) ^ b72) << 4));
        unsigned vh[4], vl[4];
        ldsm4(vh[0], vh[1], vh[2], vh[3], smB + VH_F * 4 + boff);
        ldsm4(vl[0], vl[1], vl[2], vl[3], smB + VL_F * 4 + boff);
        // tile t: b0 = m(t)/klo, b1 = m(t)/khi  (t=0: rows0-7 -> m0,m2; t=1: m1,m3)
        #pragma unroll
        for (int t = 0; t < 2; ++t) {
            mma_tf32(cacc[t], ah[0], ah[1], ah[2], ah[3], vh[t], vh[t + 2]);
            mma_tf32(cacc[t], ah[0], ah[1], ah[2], ah[3], vl[t], vl[t + 2]);
            mma_tf32(cacc[t], al[0], al[1], al[2], al[3], vh[t], vh[t + 2]);
        }
    }

    // ---- write ctx (tf32-rounded; rows < 28 only) ----
    {
        const int i0 = 16 * mt + g;          // always < 28
        #pragma unroll
        for (int t = 0; t < 2; ++t) {
            const int col = 8 * (2 * (wid >> 1) + t) + 2 * r;
            float2 v0;
            v0.x = __uint_as_float(f2tf(cacc[t][0]));
            v0.y = __uint_as_float(f2tf(cacc[t][1]));
            *(float2*)&g_ctx[base + (size_t)i0 * DMODEL + col] = v0;
            if (i0 + 8 < SEQ) {
                float2 v1;
                v1.x = __uint_as_float(f2tf(cacc[t][2]));
                v1.y = __uint_as_float(f2tf(cacc[t][3]));
                *(float2*)&g_ctx[base + (size_t)(i0 + 8) * DMODEL + col] = v1;
            }
        }
    }
}

// ---------------------------------------------------------------------------
// Launch
// ---------------------------------------------------------------------------
extern "C" void kernel_launch(void* const* d_in, const int* in_sizes, int n_in,
                              void* d_out, int out_size)
{
    const float* hidden = (const float*)d_in[0];
    const float* wq     = (const float*)d_in[1];
    const float* wk     = (const float*)d_in[2];
    const float* wv     = (const float*)d_in[3];
    const float* wo     = (const float*)d_in[4];
    const float* gamma  = (const float*)d_in[5];
    const float* beta   = (const float*)d_in[6];
    float* out = (float*)d_out;

    // Dynamic smem opt-ins. Unconditional every launch (idempotent, host-side,
    // capture-legal) — no static guards per harness rules.
    cudaFuncSetAttribute(gemm_qkv_kernel,
                         cudaFuncAttributeMaxDynamicSharedMemorySize, SMEM_BYTES);
    cudaFuncSetAttribute(gemm_out_kernel,
                         cudaFuncAttributeMaxDynamicSharedMemorySize, SMEM_BYTES);
    cudaFuncSetAttribute(attn_kernel,
                         cudaFuncAttributeMaxDynamicSharedMemorySize, ATTN_SMEM_BYTES);

    prep_weights_kernel<<<dim3(32, 32, 4), dim3(32, 8)>>>(wq, wk, wv, wo);
    ln_kernel<<<RROWS, 256>>>(hidden, gamma, beta);
    gemm_qkv_kernel<<<dim3(24, RROWS / BM), 256, SMEM_BYTES>>>();
    attn_kernel<<<dim3(NHEAD, BATCH), 256, ATTN_SMEM_BYTES>>>();
    gemm_out_kernel<<<dim3(8, RROWS / BM), 256, SMEM_BYTES>>>(out);
}